// round 13
// baseline (speedup 1.0000x reference)
#include <cuda_runtime.h>

#define BS   16
#define DD   4096
#define NN   512
#define RR   16
#define EPSV 1e-6f
#define INVT 100.0f

#define NSLICE 32     // d slices (128 d each) == grid.x of pmat/fused
#define NBTB   32
#define NCTC   16

typedef unsigned long long u64;

// ---------------- scratch ----------------
__device__ float g_b0[BS * DD * RR];
__device__ float g_b1[BS * DD * RR];
__device__ float g_coef [BS * NN * RR];
__device__ float g_Ppart[BS * NSLICE * NN * RR];   // 16 MB
__device__ float g_btbp [BS * NBTB * 256];
__device__ float g_ctcp [BS * NCTC * 256];

// ---------------- packed f32x2 ----------------
__device__ __forceinline__ void ffma2(u64& acc, u64 a, u64 b) {
    asm("fma.rn.f32x2 %0, %1, %2, %3;" : "=l"(acc) : "l"(a), "l"(b), "l"(acc));
}
__device__ __forceinline__ u64 packf2(float lo, float hi) {
    u64 r; asm("mov.b64 %0, {%1, %2};" : "=l"(r) : "f"(lo), "f"(hi)); return r;
}
__device__ __forceinline__ void unpackf2(u64 v, float& lo, float& hi) {
    asm("mov.b64 {%0, %1}, %2;" : "=f"(lo), "=f"(hi) : "l"(v));
}
__device__ __forceinline__ void fma16_2(u64* acc2, u64 xv2, const float* __restrict__ row) {
    const ulonglong2* r2 = reinterpret_cast<const ulonglong2*>(row);
#pragma unroll
    for (int q = 0; q < 4; ++q) {
        ulonglong2 p = r2[q];
        ffma2(acc2[2*q+0], xv2, p.x);
        ffma2(acc2[2*q+1], xv2, p.y);
    }
}
__device__ __forceinline__ void fma16_2_quad(u64* a0, u64* a1, u64* a2, u64* a3,
                                             u64 x0, u64 x1, u64 x2, u64 x3,
                                             const float* __restrict__ row) {
    const ulonglong2* r2 = reinterpret_cast<const ulonglong2*>(row);
#pragma unroll
    for (int q = 0; q < 4; ++q) {
        ulonglong2 p = r2[q];
        ffma2(a0[2*q+0], x0, p.x); ffma2(a0[2*q+1], x0, p.y);
        ffma2(a1[2*q+0], x1, p.x); ffma2(a1[2*q+1], x1, p.y);
        ffma2(a2[2*q+0], x2, p.x); ffma2(a2[2*q+1], x2, p.y);
        ffma2(a3[2*q+0], x3, p.x); ffma2(a3[2*q+1], x3, p.y);
    }
}
__device__ __forceinline__ void unpack_acc(const u64* acc2, float* v) {
#pragma unroll
    for (int q = 0; q < 8; ++q) unpackf2(acc2[q], v[2*q], v[2*q+1]);
}

// ---------------- helpers ----------------
__device__ __forceinline__ void load16(const float* __restrict__ src, float* v) {
    const float4* s4 = reinterpret_cast<const float4*>(src);
#pragma unroll
    for (int q = 0; q < 4; ++q) {
        float4 t = s4[q];
        v[4*q+0] = t.x; v[4*q+1] = t.y; v[4*q+2] = t.z; v[4*q+3] = t.w;
    }
}
__device__ __forceinline__ void store16(float* __restrict__ dst, const float* v) {
    float4* d4 = reinterpret_cast<float4*>(dst);
#pragma unroll
    for (int q = 0; q < 4; ++q)
        d4[q] = make_float4(v[4*q+0], v[4*q+1], v[4*q+2], v[4*q+3]);
}
__device__ __forceinline__ void mat16(float* den, const float* v, const float* __restrict__ G) {
#pragma unroll
    for (int s2 = 0; s2 < 16; ++s2) den[s2] = 0.f;
#pragma unroll
    for (int r = 0; r < 16; ++r) {
        float c = v[r];
        const float* row = &G[r * 16];
#pragma unroll
        for (int s2 = 0; s2 < 16; ++s2) den[s2] = fmaf(c, row[s2], den[s2]);
    }
}

// P-phase mainloop (shared by k_pmat0 and k_fused): bss holds this slice's bases.
// xs4 is 512x4 float4 swizzled staging. Computes P partials for all 512 n and
// emits the BtB gram partial for this slice.
__device__ __forceinline__ void p_mainloop(const float* __restrict__ xbase,
                                           const float* __restrict__ bss,
                                           float4* __restrict__ xs4,
                                           int b, int ds, int tid) {
    const int srow = tid >> 2;
    const int sc4  = tid & 3;
    const int ssw  = (srow >> 1) & 3;
    const int rsw  = (tid >> 1) & 3;

    u64 a0[8], a1[8], a2[8], a3[8];
#pragma unroll
    for (int q = 0; q < 8; ++q) { a0[q] = 0ull; a1[q] = 0ull; a2[q] = 0ull; a3[q] = 0ull; }

    float4 pre[16];
#pragma unroll
    for (int k = 0; k < 16; ++k)
        pre[k] = *reinterpret_cast<const float4*>(xbase + (size_t)(srow + k * 32) * DD + sc4 * 4);

#pragma unroll 1
    for (int t = 0; t < 8; ++t) {   // 8 tiles x 16 d = 128 d
#pragma unroll
        for (int k = 0; k < 16; ++k)
            xs4[(srow + k * 32) * 4 + (sc4 ^ ssw)] = pre[k];
        __syncthreads();
        if (t < 7) {
#pragma unroll
            for (int k = 0; k < 16; ++k)
                pre[k] = *reinterpret_cast<const float4*>(
                    xbase + (size_t)(srow + k * 32) * DD + (t + 1) * 16 + sc4 * 4);
        }
#pragma unroll
        for (int j4 = 0; j4 < 4; ++j4) {
            float4 x0 = xs4[(tid      ) * 4 + (j4 ^ rsw)];
            float4 x1 = xs4[(tid + 128) * 4 + (j4 ^ rsw)];
            float4 x2 = xs4[(tid + 256) * 4 + (j4 ^ rsw)];
            float4 x3 = xs4[(tid + 384) * 4 + (j4 ^ rsw)];
            const float* br = &bss[(t * 16 + j4 * 4) * RR];
            fma16_2_quad(a0, a1, a2, a3, packf2(x0.x,x0.x), packf2(x1.x,x1.x),
                         packf2(x2.x,x2.x), packf2(x3.x,x3.x), br);
            fma16_2_quad(a0, a1, a2, a3, packf2(x0.y,x0.y), packf2(x1.y,x1.y),
                         packf2(x2.y,x2.y), packf2(x3.y,x3.y), br + RR);
            fma16_2_quad(a0, a1, a2, a3, packf2(x0.z,x0.z), packf2(x1.z,x1.z),
                         packf2(x2.z,x2.z), packf2(x3.z,x3.z), br + 2 * RR);
            fma16_2_quad(a0, a1, a2, a3, packf2(x0.w,x0.w), packf2(x1.w,x1.w),
                         packf2(x2.w,x2.w), packf2(x3.w,x3.w), br + 3 * RR);
        }
        __syncthreads();
    }

    float acc[16];
    float* pbase = g_Ppart + (((size_t)b * NSLICE + ds) * NN) * RR;
    unpack_acc(a0, acc); store16(pbase + (size_t)(tid      ) * RR, acc);
    unpack_acc(a1, acc); store16(pbase + (size_t)(tid + 128) * RR, acc);
    unpack_acc(a2, acc); store16(pbase + (size_t)(tid + 256) * RR, acc);
    unpack_acc(a3, acc); store16(pbase + (size_t)(tid + 384) * RR, acc);

    // BtB gram partial from this slice's bases
#pragma unroll
    for (int k = 0; k < 2; ++k) {
        int p2 = tid + k * 128;
        int r = p2 >> 4, s2 = p2 & 15;
        float s0 = 0.f, s1 = 0.f, s2a = 0.f, s3 = 0.f;
#pragma unroll 4
        for (int i = 0; i < 128; i += 4) {
            s0  = fmaf(bss[(i+0)*16 + r], bss[(i+0)*16 + s2], s0);
            s1  = fmaf(bss[(i+1)*16 + r], bss[(i+1)*16 + s2], s1);
            s2a = fmaf(bss[(i+2)*16 + r], bss[(i+2)*16 + s2], s2a);
            s3  = fmaf(bss[(i+3)*16 + r], bss[(i+3)*16 + s2], s3);
        }
        g_btbp[((size_t)b * NBTB + ds) * 256 + p2] = (s0 + s1) + (s2a + s3);
    }
}

// ---------------- init P pass (bases0, no update) ----------------
// grid (32, BS), block 128
__global__ void k_pmat0(const float* __restrict__ x, const float* __restrict__ bold) {
    __shared__ __align__(16) float  smem_u[8192];    // xs4 staging (32 KB)
    __shared__ __align__(16) float  bss[128 * RR];

    const int tid = threadIdx.x;
    const int ds  = blockIdx.x;
    const int b   = blockIdx.y;

    {
        const float4* s = reinterpret_cast<const float4*>(
            bold + ((size_t)b * DD + (size_t)ds * 128) * RR);
        float4* d4 = reinterpret_cast<float4*>(bss);
#pragma unroll
        for (int i = 0; i < 4; ++i) d4[tid + i * 128] = s[tid + i * 128];
    }
    __syncthreads();
    p_mainloop(x + (size_t)b * NN * DD + (size_t)ds * 128, bss,
               reinterpret_cast<float4*>(smem_u), b, ds, tid);
}

// ---------------- FUSED: Q (complete per-slice) + bases update + P + BtB ----------------
// grid (32, BS), block 128. One X-tile read serves both GEMMs (2nd read hits L2).
__global__ void k_fused(const float* __restrict__ x,
                        const float* __restrict__ bold,
                        float* __restrict__ bnew) {
    __shared__ __align__(16) float smem_u[8192];     // Q phase: coef (32 KB); P phase: xs4
    __shared__ __align__(16) float bss[128 * RR];
    __shared__ float ctcs[256];

    const int tid = threadIdx.x;
    const int ds  = blockIdx.x;   // 0..31 (128 d)
    const int b   = blockIdx.y;

    float* cfs = smem_u;

    // stage full coef (512 x 16) + reduce CtC
    {
        const float4* s = reinterpret_cast<const float4*>(g_coef + (size_t)b * NN * RR);
        float4* dst = reinterpret_cast<float4*>(cfs);
#pragma unroll
        for (int i = 0; i < 16; ++i) dst[tid + i * 128] = s[tid + i * 128];
    }
    if (tid < 64) {
        float4 s = make_float4(0.f, 0.f, 0.f, 0.f);
#pragma unroll
        for (int sl = 0; sl < NCTC; ++sl) {
            float4 v = *reinterpret_cast<const float4*>(
                g_ctcp + ((size_t)b * NCTC + sl) * 256 + tid * 4);
            s.x += v.x; s.y += v.y; s.z += v.z; s.w += v.w;
        }
        *reinterpret_cast<float4*>(&ctcs[tid * 4]) = s;
    }

    // ---- Q phase: thread owns d = ds*128 + tid, scans ALL 512 n ----
    const int d = ds * 128 + tid;
    const float* xb = x + (size_t)b * NN * DD + d;

    float xv0[8], xv1[8];
#pragma unroll
    for (int i = 0; i < 8; ++i) xv0[i] = xb[(size_t)i * DD];
#pragma unroll
    for (int i = 0; i < 8; ++i) xv1[i] = xb[(size_t)(8 + i) * DD];

    __syncthreads();   // cfs + ctcs ready

    u64 acc2[8];
#pragma unroll
    for (int q = 0; q < 8; ++q) acc2[q] = 0ull;

#pragma unroll 1
    for (int n0 = 0; n0 < NN; n0 += 16) {
        const bool pf = (n0 + 16) < NN;
#pragma unroll
        for (int i = 0; i < 8; ++i)
            fma16_2(acc2, packf2(xv0[i], xv0[i]), &cfs[(n0 + i) * RR]);
        if (pf) {
#pragma unroll
            for (int i = 0; i < 8; ++i) xv0[i] = xb[(size_t)(n0 + 16 + i) * DD];
        }
#pragma unroll
        for (int i = 0; i < 8; ++i)
            fma16_2(acc2, packf2(xv1[i], xv1[i]), &cfs[(n0 + 8 + i) * RR]);
        if (pf) {
#pragma unroll
            for (int i = 0; i < 8; ++i) xv1[i] = xb[(size_t)(n0 + 24 + i) * DD];
        }
    }

    // ---- bases multiplicative update (Q is complete: all n summed) ----
    {
        float q[16];
        unpack_acc(acc2, q);
        float ob[16], den[16];
        load16(bold + ((size_t)b * DD + d) * RR, ob);
        mat16(den, ob, ctcs);
#pragma unroll
        for (int r = 0; r < 16; ++r) ob[r] = ob[r] * q[r] / (den[r] + EPSV);
        store16(bnew + ((size_t)b * DD + d) * RR, ob);
        store16(&bss[tid * RR], ob);
    }
    __syncthreads();   // bss ready; cfs no longer needed (aliased as xs4)

    // ---- P phase: re-read same X tile (L2-hot), quad-n blocking ----
    p_mainloop(x + (size_t)b * NN * DD + (size_t)ds * 128, bss,
               reinterpret_cast<float4*>(smem_u), b, ds, tid);
}

// ---------------- coef kernel: 32 n per block, 4-way parallel gather ----------------
// grid (16, BS), block 128
__device__ __forceinline__ void coef_body(bool init) {
    __shared__ float btbs[256];
    __shared__ __align__(16) float pg[4][32][16];
    __shared__ float smcf[32][17];
    const int tid = threadIdx.x;
    const int nc  = blockIdx.x;
    const int b   = blockIdx.y;

    if (tid < 64) {
        float4 s = make_float4(0.f, 0.f, 0.f, 0.f);
#pragma unroll
        for (int sl = 0; sl < NBTB; ++sl) {
            float4 v = *reinterpret_cast<const float4*>(
                g_btbp + ((size_t)b * NBTB + sl) * 256 + tid * 4);
            s.x += v.x; s.y += v.y; s.z += v.z; s.w += v.w;
        }
        *reinterpret_cast<float4*>(&btbs[tid * 4]) = s;
    }

    const int nl = tid & 31;
    const int g  = tid >> 5;
    const int n  = nc * 32 + nl;
    {
        float p[16];
#pragma unroll
        for (int r = 0; r < 16; ++r) p[r] = 0.f;
#pragma unroll
        for (int k = 0; k < 8; ++k) {
            const float4* pp = reinterpret_cast<const float4*>(
                g_Ppart + (((size_t)b * NSLICE + g * 8 + k) * NN + n) * RR);
#pragma unroll
            for (int q = 0; q < 4; ++q) {
                float4 v = pp[q];
                p[4*q+0] += v.x; p[4*q+1] += v.y; p[4*q+2] += v.z; p[4*q+3] += v.w;
            }
        }
        store16(&pg[g][nl][0], p);
    }
    __syncthreads();

    if (tid < 32) {
        float p[16];
#pragma unroll
        for (int r = 0; r < 16; ++r)
            p[r] = (pg[0][tid][r] + pg[1][tid][r]) + (pg[2][tid][r] + pg[3][tid][r]);

        const int nn = nc * 32 + tid;
        float cf[16];
        if (init) {
            float m = p[0];
#pragma unroll
            for (int r = 1; r < 16; ++r) m = fmaxf(m, p[r]);
            float s = 0.f;
#pragma unroll
            for (int r = 0; r < 16; ++r) { cf[r] = __expf(INVT * (p[r] - m)); s += cf[r]; }
            float inv = 1.f / s;
#pragma unroll
            for (int r = 0; r < 16; ++r) cf[r] *= inv;
        } else {
            load16(g_coef + ((size_t)b * NN + nn) * RR, cf);
        }
        float den[16];
        mat16(den, cf, btbs);
#pragma unroll
        for (int r = 0; r < 16; ++r) cf[r] = cf[r] * p[r] / (den[r] + EPSV);
        store16(g_coef + ((size_t)b * NN + nn) * RR, cf);
#pragma unroll
        for (int r = 0; r < 16; ++r) smcf[tid][r] = cf[r];
    }
    __syncthreads();

#pragma unroll
    for (int k = 0; k < 2; ++k) {
        int p2 = tid + k * 128;
        int r = p2 >> 4, s2 = p2 & 15;
        float s0 = 0.f, s1 = 0.f;
#pragma unroll
        for (int i = 0; i < 32; i += 2) {
            s0 = fmaf(smcf[i][r],   smcf[i][s2],   s0);
            s1 = fmaf(smcf[i+1][r], smcf[i+1][s2], s1);
        }
        g_ctcp[((size_t)b * NCTC + nc) * 256 + p2] = s0 + s1;
    }
}
__global__ void __launch_bounds__(128) k_coef_initupd() { coef_body(true); }
__global__ void __launch_bounds__(128) k_coef_upd()     { coef_body(false); }

// ---------------- reconstruction: 2 d per thread ----------------
// grid (16, BS), block 128
__global__ void k_out(const float* __restrict__ bfin, float* __restrict__ out) {
    __shared__ __align__(16) float cfs[NN * RR];
    const int tid = threadIdx.x;
    const int dc  = blockIdx.x;
    const int b   = blockIdx.y;
    {
        const float4* s = reinterpret_cast<const float4*>(g_coef + (size_t)b * NN * RR);
        float4* dst = reinterpret_cast<float4*>(cfs);
#pragma unroll
        for (int i = 0; i < 16; ++i) dst[tid + i * 128] = s[tid + i * 128];
    }
    __syncthreads();

    const int d = dc * 256 + tid * 2;
    float bsv[16];
    u64 b0[8], b1[8];
    load16(bfin + ((size_t)b * DD + d) * RR, bsv);
#pragma unroll
    for (int q = 0; q < 8; ++q) b0[q] = packf2(bsv[2*q], bsv[2*q+1]);
    load16(bfin + ((size_t)b * DD + d + 1) * RR, bsv);
#pragma unroll
    for (int q = 0; q < 8; ++q) b1[q] = packf2(bsv[2*q], bsv[2*q+1]);

    float* ob = out + (size_t)b * NN * DD + d;
#pragma unroll 2
    for (int n = 0; n < NN; ++n) {
        const ulonglong2* c2 = reinterpret_cast<const ulonglong2*>(&cfs[n * RR]);
        u64 s0a = 0ull, s0b = 0ull, s1a = 0ull, s1b = 0ull;
#pragma unroll
        for (int q = 0; q < 4; ++q) {
            ulonglong2 pq = c2[q];
            ffma2(s0a, b0[2*q+0], pq.x);
            ffma2(s0b, b0[2*q+1], pq.y);
            ffma2(s1a, b1[2*q+0], pq.x);
            ffma2(s1b, b1[2*q+1], pq.y);
        }
        float u0, u1, v0, v1, w0, w1, z0, z1;
        unpackf2(s0a, u0, u1); unpackf2(s0b, v0, v1);
        unpackf2(s1a, w0, w1); unpackf2(s1b, z0, z1);
        float2 o;
        o.x = (u0 + u1) + (v0 + v1);
        o.y = (w0 + w1) + (z0 + z1);
        *reinterpret_cast<float2*>(ob + (size_t)n * DD) = o;
    }
}

// ---------------- launch ----------------
extern "C" void kernel_launch(void* const* d_in, const int* in_sizes, int n_in,
                              void* d_out, int out_size) {
    (void)in_sizes; (void)n_in; (void)out_size;
    const float* x     = (const float*)d_in[0];
    const float* bases = (const float*)d_in[1];
    float* out = (float*)d_out;

    float* b0p; cudaGetSymbolAddress((void**)&b0p, g_b0);
    float* b1p; cudaGetSymbolAddress((void**)&b1p, g_b1);

    // P(X, bases0) + BtB(bases0), then softmax init + coef update #1
    k_pmat0<<<dim3(NSLICE, BS), 128>>>(x, bases);
    k_coef_initupd<<<dim3(16, BS), 128>>>();

    const float* boldp = bases;
    float* bnewp = b0p;
    for (int it = 0; it < 7; ++it) {
        k_fused<<<dim3(NSLICE, BS), 128>>>(x, boldp, bnewp);  // Q + bases upd + P + BtB
        k_coef_upd<<<dim3(16, BS), 128>>>();                  // coef upd + CtC
        boldp = bnewp;
        bnewp = (bnewp == b0p) ? b1p : b0p;
    }

    k_out<<<dim3(16, BS), 128>>>(boldp, out);
}

// round 14
// speedup vs baseline: 1.2148x; 1.2148x over previous
#include <cuda_runtime.h>

#define BS   16
#define DD   4096
#define NN   512
#define RR   16
#define EPSV 1e-6f
#define INVT 100.0f

#define NSLICE 16     // P partial slices (256 d each)
#define NBTB   16
#define NCTC   16
#define NSPL   2      // qmat n-split

typedef unsigned long long u64;

// ---------------- scratch ----------------
__device__ float g_b0[BS * DD * RR];
__device__ float g_b1[BS * DD * RR];
__device__ float g_coef [BS * NN * RR];
__device__ float g_Ppart[BS * NSLICE * NN * RR];   // 8 MB
__device__ float g_Qpart[BS * NSPL * DD * RR];     // 8 MB
__device__ float g_btbp [BS * NBTB * 256];
__device__ float g_ctcp [BS * NCTC * 256];

// ---------------- packed f32x2 ----------------
__device__ __forceinline__ void ffma2(u64& acc, u64 a, u64 b) {
    asm("fma.rn.f32x2 %0, %1, %2, %3;" : "=l"(acc) : "l"(a), "l"(b), "l"(acc));
}
__device__ __forceinline__ u64 packf2(float lo, float hi) {
    u64 r; asm("mov.b64 %0, {%1, %2};" : "=l"(r) : "f"(lo), "f"(hi)); return r;
}
__device__ __forceinline__ void unpackf2(u64 v, float& lo, float& hi) {
    asm("mov.b64 {%0, %1}, %2;" : "=f"(lo), "=f"(hi) : "l"(v));
}
__device__ __forceinline__ void fma16_2_dual(u64* a0, u64* a1, u64 x0, u64 x1,
                                             const float* __restrict__ row) {
    const ulonglong2* r2 = reinterpret_cast<const ulonglong2*>(row);
#pragma unroll
    for (int q = 0; q < 4; ++q) {
        ulonglong2 p = r2[q];
        ffma2(a0[2*q+0], x0, p.x);
        ffma2(a0[2*q+1], x0, p.y);
        ffma2(a1[2*q+0], x1, p.x);
        ffma2(a1[2*q+1], x1, p.y);
    }
}
__device__ __forceinline__ void fma16_2_quad(u64* a0, u64* a1, u64* a2, u64* a3,
                                             u64 x0, u64 x1, u64 x2, u64 x3,
                                             const float* __restrict__ row) {
    const ulonglong2* r2 = reinterpret_cast<const ulonglong2*>(row);
#pragma unroll
    for (int q = 0; q < 4; ++q) {
        ulonglong2 p = r2[q];
        ffma2(a0[2*q+0], x0, p.x); ffma2(a0[2*q+1], x0, p.y);
        ffma2(a1[2*q+0], x1, p.x); ffma2(a1[2*q+1], x1, p.y);
        ffma2(a2[2*q+0], x2, p.x); ffma2(a2[2*q+1], x2, p.y);
        ffma2(a3[2*q+0], x3, p.x); ffma2(a3[2*q+1], x3, p.y);
    }
}
__device__ __forceinline__ void unpack_acc(const u64* acc2, float* v) {
#pragma unroll
    for (int q = 0; q < 8; ++q) unpackf2(acc2[q], v[2*q], v[2*q+1]);
}

// ---------------- helpers ----------------
__device__ __forceinline__ void load16(const float* __restrict__ src, float* v) {
    const float4* s4 = reinterpret_cast<const float4*>(src);
#pragma unroll
    for (int q = 0; q < 4; ++q) {
        float4 t = s4[q];
        v[4*q+0] = t.x; v[4*q+1] = t.y; v[4*q+2] = t.z; v[4*q+3] = t.w;
    }
}
__device__ __forceinline__ void store16(float* __restrict__ dst, const float* v) {
    float4* d4 = reinterpret_cast<float4*>(dst);
#pragma unroll
    for (int q = 0; q < 4; ++q)
        d4[q] = make_float4(v[4*q+0], v[4*q+1], v[4*q+2], v[4*q+3]);
}
__device__ __forceinline__ void mat16(float* den, const float* v, const float* __restrict__ G) {
#pragma unroll
    for (int s2 = 0; s2 < 16; ++s2) den[s2] = 0.f;
#pragma unroll
    for (int r = 0; r < 16; ++r) {
        float c = v[r];
        const float* row = &G[r * 16];
#pragma unroll
        for (int s2 = 0; s2 < 16; ++s2) den[s2] = fmaf(c, row[s2], den[s2]);
    }
}

// ---------------- P pass: quad-n mainloop over a 256-d slice (+ bases upd + BtB) ----------------
// grid (16, BS), block 128. smem: bss 16KB + xs4 32KB + ctcs 1KB.
template <bool UPD>
__global__ void k_pmat(const float* __restrict__ x,
                       const float* __restrict__ bold,
                       float* __restrict__ bnew) {
    __shared__ __align__(16) float  bss[256 * RR];   // bases slice 256 d x 16 r
    __shared__ __align__(16) float4 xs4[512 * 4];    // x tile 512 n x 16 d, swizzled
    __shared__ float ctcs[256];

    const int tid = threadIdx.x;
    const int ds  = blockIdx.x;   // 0..15 (256 d each)
    const int b   = blockIdx.y;

    if (UPD) {
        if (tid < 64) {
            float4 s = make_float4(0.f, 0.f, 0.f, 0.f);
#pragma unroll
            for (int sl = 0; sl < NCTC; ++sl) {
                float4 v = *reinterpret_cast<const float4*>(
                    g_ctcp + ((size_t)b * NCTC + sl) * 256 + tid * 4);
                s.x += v.x; s.y += v.y; s.z += v.z; s.w += v.w;
            }
            *reinterpret_cast<float4*>(&ctcs[tid * 4]) = s;
        }
        __syncthreads();
        // register-lean update: 2 rows per thread, quads processed sequentially
#pragma unroll
        for (int rr = 0; rr < 2; ++rr) {
            const int ld = tid * 2 + rr;
            const int gd = ds * 256 + ld;
            float ob[16];
            load16(bold + ((size_t)b * DD + gd) * RR, ob);
            const float4* q0 = reinterpret_cast<const float4*>(
                g_Qpart + (((size_t)b * NSPL + 0) * DD + gd) * RR);
            const float4* q1 = reinterpret_cast<const float4*>(
                g_Qpart + (((size_t)b * NSPL + 1) * DD + gd) * RR);
#pragma unroll
            for (int sq = 0; sq < 4; ++sq) {
                float d0 = 0.f, d1 = 0.f, d2 = 0.f, d3 = 0.f;
#pragma unroll
                for (int r = 0; r < 16; ++r) {
                    float c = ob[r];
                    const float* row = &ctcs[r * 16 + sq * 4];
                    d0 = fmaf(c, row[0], d0);
                    d1 = fmaf(c, row[1], d1);
                    d2 = fmaf(c, row[2], d2);
                    d3 = fmaf(c, row[3], d3);
                }
                float4 qa = q0[sq], qb = q1[sq];
                float4 o;
                o.x = ob[4*sq+0] * (qa.x + qb.x) / (d0 + EPSV);
                o.y = ob[4*sq+1] * (qa.y + qb.y) / (d1 + EPSV);
                o.z = ob[4*sq+2] * (qa.z + qb.z) / (d2 + EPSV);
                o.w = ob[4*sq+3] * (qa.w + qb.w) / (d3 + EPSV);
                *reinterpret_cast<float4*>(&bss[ld * RR + sq * 4]) = o;
                *reinterpret_cast<float4*>(bnew + ((size_t)b * DD + gd) * RR + sq * 4) = o;
            }
        }
    } else {
        const float4* s = reinterpret_cast<const float4*>(
            bold + ((size_t)b * DD + (size_t)ds * 256) * RR);
        float4* d4 = reinterpret_cast<float4*>(bss);
#pragma unroll
        for (int i = 0; i < 8; ++i) d4[tid + i * 128] = s[tid + i * 128];
    }

    const float* xbase = x + (size_t)b * NN * DD + (size_t)ds * 256;
    const int srow = tid >> 2;                // 0..31 staging row base
    const int sc4  = tid & 3;                 // float4 col within 16-d tile
    const int ssw  = (srow >> 1) & 3;         // store swizzle
    const int rsw  = (tid >> 1) & 3;          // read swizzle

    u64 a0[8], a1[8], a2[8], a3[8];
#pragma unroll
    for (int q = 0; q < 8; ++q) { a0[q] = 0ull; a1[q] = 0ull; a2[q] = 0ull; a3[q] = 0ull; }

    float4 pre[16];
#pragma unroll
    for (int k = 0; k < 16; ++k)
        pre[k] = *reinterpret_cast<const float4*>(xbase + (size_t)(srow + k * 32) * DD + sc4 * 4);

    __syncthreads();   // bss ready

#pragma unroll 1
    for (int t = 0; t < 16; ++t) {   // 16 tiles x 16 d = 256 d
#pragma unroll
        for (int k = 0; k < 16; ++k)
            xs4[(srow + k * 32) * 4 + (sc4 ^ ssw)] = pre[k];
        __syncthreads();
        if (t < 15) {
#pragma unroll
            for (int k = 0; k < 16; ++k)
                pre[k] = *reinterpret_cast<const float4*>(
                    xbase + (size_t)(srow + k * 32) * DD + (t + 1) * 16 + sc4 * 4);
        }
#pragma unroll
        for (int j4 = 0; j4 < 4; ++j4) {
            float4 x0 = xs4[(tid      ) * 4 + (j4 ^ rsw)];
            float4 x1 = xs4[(tid + 128) * 4 + (j4 ^ rsw)];
            float4 x2 = xs4[(tid + 256) * 4 + (j4 ^ rsw)];
            float4 x3 = xs4[(tid + 384) * 4 + (j4 ^ rsw)];
            const float* br = &bss[(t * 16 + j4 * 4) * RR];
            fma16_2_quad(a0, a1, a2, a3, packf2(x0.x,x0.x), packf2(x1.x,x1.x),
                         packf2(x2.x,x2.x), packf2(x3.x,x3.x), br);
            fma16_2_quad(a0, a1, a2, a3, packf2(x0.y,x0.y), packf2(x1.y,x1.y),
                         packf2(x2.y,x2.y), packf2(x3.y,x3.y), br + RR);
            fma16_2_quad(a0, a1, a2, a3, packf2(x0.z,x0.z), packf2(x1.z,x1.z),
                         packf2(x2.z,x2.z), packf2(x3.z,x3.z), br + 2 * RR);
            fma16_2_quad(a0, a1, a2, a3, packf2(x0.w,x0.w), packf2(x1.w,x1.w),
                         packf2(x2.w,x2.w), packf2(x3.w,x3.w), br + 3 * RR);
        }
        __syncthreads();
    }

    float acc[16];
    float* pbase = g_Ppart + (((size_t)b * NSLICE + ds) * NN) * RR;
    unpack_acc(a0, acc); store16(pbase + (size_t)(tid      ) * RR, acc);
    unpack_acc(a1, acc); store16(pbase + (size_t)(tid + 128) * RR, acc);
    unpack_acc(a2, acc); store16(pbase + (size_t)(tid + 256) * RR, acc);
    unpack_acc(a3, acc); store16(pbase + (size_t)(tid + 384) * RR, acc);

    // BtB gram partial from this slice's bases (256 rows)
#pragma unroll
    for (int k = 0; k < 2; ++k) {
        int p2 = tid + k * 128;
        int r = p2 >> 4, s2 = p2 & 15;
        float s0 = 0.f, s1 = 0.f, s2a = 0.f, s3 = 0.f;
#pragma unroll 4
        for (int i = 0; i < 256; i += 4) {
            s0  = fmaf(bss[(i+0)*16 + r], bss[(i+0)*16 + s2], s0);
            s1  = fmaf(bss[(i+1)*16 + r], bss[(i+1)*16 + s2], s1);
            s2a = fmaf(bss[(i+2)*16 + r], bss[(i+2)*16 + s2], s2a);
            s3  = fmaf(bss[(i+3)*16 + r], bss[(i+3)*16 + s2], s3);
        }
        g_btbp[((size_t)b * NBTB + ds) * 256 + p2] = (s0 + s1) + (s2a + s3);
    }
}

// ---------------- coef kernel: 32 n per block, 4 groups x 4 slices ----------------
// grid (16, BS), block 128
__device__ __forceinline__ void coef_body(bool init) {
    __shared__ float btbs[256];
    __shared__ __align__(16) float pg[4][32][16];
    __shared__ float smcf[32][17];
    const int tid = threadIdx.x;
    const int nc  = blockIdx.x;
    const int b   = blockIdx.y;

    if (tid < 64) {
        float4 s = make_float4(0.f, 0.f, 0.f, 0.f);
#pragma unroll
        for (int sl = 0; sl < NBTB; ++sl) {
            float4 v = *reinterpret_cast<const float4*>(
                g_btbp + ((size_t)b * NBTB + sl) * 256 + tid * 4);
            s.x += v.x; s.y += v.y; s.z += v.z; s.w += v.w;
        }
        *reinterpret_cast<float4*>(&btbs[tid * 4]) = s;
    }

    const int nl = tid & 31;
    const int g  = tid >> 5;
    const int n  = nc * 32 + nl;
    {
        float p[16];
#pragma unroll
        for (int r = 0; r < 16; ++r) p[r] = 0.f;
#pragma unroll
        for (int k = 0; k < 4; ++k) {
            const float4* pp = reinterpret_cast<const float4*>(
                g_Ppart + (((size_t)b * NSLICE + g * 4 + k) * NN + n) * RR);
#pragma unroll
            for (int q = 0; q < 4; ++q) {
                float4 v = pp[q];
                p[4*q+0] += v.x; p[4*q+1] += v.y; p[4*q+2] += v.z; p[4*q+3] += v.w;
            }
        }
        store16(&pg[g][nl][0], p);
    }
    __syncthreads();

    if (tid < 32) {
        float p[16];
#pragma unroll
        for (int r = 0; r < 16; ++r)
            p[r] = (pg[0][tid][r] + pg[1][tid][r]) + (pg[2][tid][r] + pg[3][tid][r]);

        const int nn = nc * 32 + tid;
        float cf[16];
        if (init) {
            float m = p[0];
#pragma unroll
            for (int r = 1; r < 16; ++r) m = fmaxf(m, p[r]);
            float s = 0.f;
#pragma unroll
            for (int r = 0; r < 16; ++r) { cf[r] = __expf(INVT * (p[r] - m)); s += cf[r]; }
            float inv = 1.f / s;
#pragma unroll
            for (int r = 0; r < 16; ++r) cf[r] *= inv;
        } else {
            load16(g_coef + ((size_t)b * NN + nn) * RR, cf);
        }
        float den[16];
        mat16(den, cf, btbs);
#pragma unroll
        for (int r = 0; r < 16; ++r) cf[r] = cf[r] * p[r] / (den[r] + EPSV);
        store16(g_coef + ((size_t)b * NN + nn) * RR, cf);
#pragma unroll
        for (int r = 0; r < 16; ++r) smcf[tid][r] = cf[r];
    }
    __syncthreads();

#pragma unroll
    for (int k = 0; k < 2; ++k) {
        int p2 = tid + k * 128;
        int r = p2 >> 4, s2 = p2 & 15;
        float s0 = 0.f, s1 = 0.f;
#pragma unroll
        for (int i = 0; i < 32; i += 2) {
            s0 = fmaf(smcf[i][r],   smcf[i][s2],   s0);
            s1 = fmaf(smcf[i+1][r], smcf[i+1][s2], s1);
        }
        g_ctcp[((size_t)b * NCTC + nc) * 256 + p2] = s0 + s1;
    }
}
__global__ void __launch_bounds__(128) k_coef_initupd() { coef_body(true); }
__global__ void __launch_bounds__(128) k_coef_upd()     { coef_body(false); }

// ---------------- Q pass (R9 version): pure partial GEMM, split n 2 ways ----------------
// grid (16, 2, BS), block 128, 2 d per thread
__global__ void k_qmat(const float* __restrict__ x) {
    __shared__ __align__(16) float cfs[256 * RR];   // 16KB coef half
    const int tid = threadIdx.x;
    const int dc  = blockIdx.x;
    const int h   = blockIdx.y;
    const int b   = blockIdx.z;
    {
        const float4* s = reinterpret_cast<const float4*>(
            g_coef + ((size_t)b * NN + (size_t)h * 256) * RR);
        float4* dst = reinterpret_cast<float4*>(cfs);
#pragma unroll
        for (int i = 0; i < 8; ++i) dst[tid + i * 128] = s[tid + i * 128];
    }

    const int d = dc * 256 + tid * 2;
    const float* xb = x + ((size_t)b * NN + (size_t)h * 256) * DD + d;

    float2 xv0[8], xv1[8];
#pragma unroll
    for (int i = 0; i < 8; ++i) xv0[i] = *reinterpret_cast<const float2*>(xb + (size_t)i * DD);
#pragma unroll
    for (int i = 0; i < 8; ++i) xv1[i] = *reinterpret_cast<const float2*>(xb + (size_t)(8 + i) * DD);

    __syncthreads();

    u64 a0[8], a1[8];
#pragma unroll
    for (int q = 0; q < 8; ++q) { a0[q] = 0ull; a1[q] = 0ull; }

#pragma unroll 1
    for (int n0 = 0; n0 < 256; n0 += 16) {
        const bool pf = (n0 + 16) < 256;
#pragma unroll
        for (int i = 0; i < 8; ++i)
            fma16_2_dual(a0, a1, packf2(xv0[i].x, xv0[i].x), packf2(xv0[i].y, xv0[i].y),
                         &cfs[(n0 + i) * RR]);
        if (pf) {
#pragma unroll
            for (int i = 0; i < 8; ++i)
                xv0[i] = *reinterpret_cast<const float2*>(xb + (size_t)(n0 + 16 + i) * DD);
        }
#pragma unroll
        for (int i = 0; i < 8; ++i)
            fma16_2_dual(a0, a1, packf2(xv1[i].x, xv1[i].x), packf2(xv1[i].y, xv1[i].y),
                         &cfs[(n0 + 8 + i) * RR]);
        if (pf) {
#pragma unroll
            for (int i = 0; i < 8; ++i)
                xv1[i] = *reinterpret_cast<const float2*>(xb + (size_t)(n0 + 24 + i) * DD);
        }
    }

    float acc[16];
    unpack_acc(a0, acc);
    store16(g_Qpart + (((size_t)b * NSPL + h) * DD + d) * RR, acc);
    unpack_acc(a1, acc);
    store16(g_Qpart + (((size_t)b * NSPL + h) * DD + d + 1) * RR, acc);
}

// ---------------- reconstruction: 2 d per thread ----------------
// grid (16, BS), block 128
__global__ void k_out(const float* __restrict__ bfin, float* __restrict__ out) {
    __shared__ __align__(16) float cfs[NN * RR];
    const int tid = threadIdx.x;
    const int dc  = blockIdx.x;
    const int b   = blockIdx.y;
    {
        const float4* s = reinterpret_cast<const float4*>(g_coef + (size_t)b * NN * RR);
        float4* dst = reinterpret_cast<float4*>(cfs);
#pragma unroll
        for (int i = 0; i < 16; ++i) dst[tid + i * 128] = s[tid + i * 128];
    }
    __syncthreads();

    const int d = dc * 256 + tid * 2;
    float bsv[16];
    u64 b0[8], b1[8];
    load16(bfin + ((size_t)b * DD + d) * RR, bsv);
#pragma unroll
    for (int q = 0; q < 8; ++q) b0[q] = packf2(bsv[2*q], bsv[2*q+1]);
    load16(bfin + ((size_t)b * DD + d + 1) * RR, bsv);
#pragma unroll
    for (int q = 0; q < 8; ++q) b1[q] = packf2(bsv[2*q], bsv[2*q+1]);

    float* ob = out + (size_t)b * NN * DD + d;
#pragma unroll 2
    for (int n = 0; n < NN; ++n) {
        const ulonglong2* c2 = reinterpret_cast<const ulonglong2*>(&cfs[n * RR]);
        u64 s0a = 0ull, s0b = 0ull, s1a = 0ull, s1b = 0ull;
#pragma unroll
        for (int q = 0; q < 4; ++q) {
            ulonglong2 pq = c2[q];
            ffma2(s0a, b0[2*q+0], pq.x);
            ffma2(s0b, b0[2*q+1], pq.y);
            ffma2(s1a, b1[2*q+0], pq.x);
            ffma2(s1b, b1[2*q+1], pq.y);
        }
        float u0, u1, v0, v1, w0, w1, z0, z1;
        unpackf2(s0a, u0, u1); unpackf2(s0b, v0, v1);
        unpackf2(s1a, w0, w1); unpackf2(s1b, z0, z1);
        float2 o;
        o.x = (u0 + u1) + (v0 + v1);
        o.y = (w0 + w1) + (z0 + z1);
        *reinterpret_cast<float2*>(ob + (size_t)n * DD) = o;
    }
}

// ---------------- launch ----------------
extern "C" void kernel_launch(void* const* d_in, const int* in_sizes, int n_in,
                              void* d_out, int out_size) {
    (void)in_sizes; (void)n_in; (void)out_size;
    const float* x     = (const float*)d_in[0];
    const float* bases = (const float*)d_in[1];
    float* out = (float*)d_out;

    float* b0p; cudaGetSymbolAddress((void**)&b0p, g_b0);
    float* b1p; cudaGetSymbolAddress((void**)&b1p, g_b1);

    // P(X, bases0) + BtB(bases0), then softmax init + coef update #1
    k_pmat<false><<<dim3(NSLICE, BS), 128>>>(x, bases, nullptr);
    k_coef_initupd<<<dim3(16, BS), 128>>>();

    const float* boldp = bases;
    float* bnewp = b0p;
    for (int it = 0; it < 7; ++it) {
        k_qmat<<<dim3(16, NSPL, BS), 128>>>(x);                   // Q partials
        k_pmat<true><<<dim3(NSLICE, BS), 128>>>(x, boldp, bnewp); // bases upd + P + BtB
        k_coef_upd<<<dim3(16, BS), 128>>>();                      // coef upd + CtC
        boldp = bnewp;
        bnewp = (bnewp == b0p) ? b1p : b0p;
    }

    k_out<<<dim3(16, BS), 128>>>(boldp, out);
}

// round 15
// speedup vs baseline: 1.2252x; 1.0086x over previous
#include <cuda_runtime.h>
#include <cstdint>

#define BS   16
#define DD   4096
#define NN   512
#define RR   16
#define EPSV 1e-6f
#define INVT 100.0f

#define NSLICE 16     // P partial slices (256 d each)
#define NBTB   16
#define NCTC   16
#define NSPL   2      // qmat n-split

typedef unsigned long long u64;

// dynamic smem layout for k_pmat (floats): bss[4096] | ctcs[256] | xs4 double buf [2*2048 float4]
#define PM_SMEM_FLOATS (4096 + 256 + 2 * 2048 * 4)
#define PM_SMEM_BYTES  (PM_SMEM_FLOATS * 4)

// ---------------- scratch ----------------
__device__ float g_b0[BS * DD * RR];
__device__ float g_b1[BS * DD * RR];
__device__ float g_coef [BS * NN * RR];
__device__ float g_Ppart[BS * NSLICE * NN * RR];   // 8 MB
__device__ float g_Qpart[BS * NSPL * DD * RR];     // 8 MB
__device__ float g_btbp [BS * NBTB * 256];
__device__ float g_ctcp [BS * NCTC * 256];

// ---------------- packed f32x2 ----------------
__device__ __forceinline__ void ffma2(u64& acc, u64 a, u64 b) {
    asm("fma.rn.f32x2 %0, %1, %2, %3;" : "=l"(acc) : "l"(a), "l"(b), "l"(acc));
}
__device__ __forceinline__ u64 packf2(float lo, float hi) {
    u64 r; asm("mov.b64 %0, {%1, %2};" : "=l"(r) : "f"(lo), "f"(hi)); return r;
}
__device__ __forceinline__ void unpackf2(u64 v, float& lo, float& hi) {
    asm("mov.b64 {%0, %1}, %2;" : "=f"(lo), "=f"(hi) : "l"(v));
}
__device__ __forceinline__ void fma16_2_dual(u64* a0, u64* a1, u64 x0, u64 x1,
                                             const float* __restrict__ row) {
    const ulonglong2* r2 = reinterpret_cast<const ulonglong2*>(row);
#pragma unroll
    for (int q = 0; q < 4; ++q) {
        ulonglong2 p = r2[q];
        ffma2(a0[2*q+0], x0, p.x);
        ffma2(a0[2*q+1], x0, p.y);
        ffma2(a1[2*q+0], x1, p.x);
        ffma2(a1[2*q+1], x1, p.y);
    }
}
__device__ __forceinline__ void fma16_2_quad(u64* a0, u64* a1, u64* a2, u64* a3,
                                             u64 x0, u64 x1, u64 x2, u64 x3,
                                             const float* __restrict__ row) {
    const ulonglong2* r2 = reinterpret_cast<const ulonglong2*>(row);
#pragma unroll
    for (int q = 0; q < 4; ++q) {
        ulonglong2 p = r2[q];
        ffma2(a0[2*q+0], x0, p.x); ffma2(a0[2*q+1], x0, p.y);
        ffma2(a1[2*q+0], x1, p.x); ffma2(a1[2*q+1], x1, p.y);
        ffma2(a2[2*q+0], x2, p.x); ffma2(a2[2*q+1], x2, p.y);
        ffma2(a3[2*q+0], x3, p.x); ffma2(a3[2*q+1], x3, p.y);
    }
}
__device__ __forceinline__ void unpack_acc(const u64* acc2, float* v) {
#pragma unroll
    for (int q = 0; q < 8; ++q) unpackf2(acc2[q], v[2*q], v[2*q+1]);
}

// ---------------- cp.async helpers ----------------
__device__ __forceinline__ uint32_t smem_u32(const void* p) {
    return (uint32_t)__cvta_generic_to_shared(p);
}
__device__ __forceinline__ void cp16(uint32_t dst, const float* __restrict__ src) {
    asm volatile("cp.async.ca.shared.global [%0], [%1], 16;" :: "r"(dst), "l"(src));
}
__device__ __forceinline__ void cp_commit() {
    asm volatile("cp.async.commit_group;");
}
template <int N>
__device__ __forceinline__ void cp_wait() {
    asm volatile("cp.async.wait_group %0;" :: "n"(N));
}

// ---------------- helpers ----------------
__device__ __forceinline__ void load16(const float* __restrict__ src, float* v) {
    const float4* s4 = reinterpret_cast<const float4*>(src);
#pragma unroll
    for (int q = 0; q < 4; ++q) {
        float4 t = s4[q];
        v[4*q+0] = t.x; v[4*q+1] = t.y; v[4*q+2] = t.z; v[4*q+3] = t.w;
    }
}
__device__ __forceinline__ void store16(float* __restrict__ dst, const float* v) {
    float4* d4 = reinterpret_cast<float4*>(dst);
#pragma unroll
    for (int q = 0; q < 4; ++q)
        d4[q] = make_float4(v[4*q+0], v[4*q+1], v[4*q+2], v[4*q+3]);
}
__device__ __forceinline__ void mat16(float* den, const float* v, const float* __restrict__ G) {
#pragma unroll
    for (int s2 = 0; s2 < 16; ++s2) den[s2] = 0.f;
#pragma unroll
    for (int r = 0; r < 16; ++r) {
        float c = v[r];
        const float* row = &G[r * 16];
#pragma unroll
        for (int s2 = 0; s2 < 16; ++s2) den[s2] = fmaf(c, row[s2], den[s2]);
    }
}

// ---------------- P pass: quad-n, cp.async double-buffered staging ----------------
// grid (16, BS), block 128. dynamic smem: bss 16KB + ctcs 1KB + xs 64KB
template <bool UPD>
__global__ void k_pmat(const float* __restrict__ x,
                       const float* __restrict__ bold,
                       float* __restrict__ bnew) {
    extern __shared__ __align__(16) float smem_dyn[];
    float*  bss  = smem_dyn;                                   // 4096 floats
    float*  ctcs = smem_dyn + 4096;                            // 256 floats
    float4* xsb  = reinterpret_cast<float4*>(smem_dyn + 4352); // 2 x 2048 float4

    const int tid = threadIdx.x;
    const int ds  = blockIdx.x;   // 0..15 (256 d each)
    const int b   = blockIdx.y;

    if (UPD) {
        if (tid < 64) {
            float4 s = make_float4(0.f, 0.f, 0.f, 0.f);
#pragma unroll
            for (int sl = 0; sl < NCTC; ++sl) {
                float4 v = *reinterpret_cast<const float4*>(
                    g_ctcp + ((size_t)b * NCTC + sl) * 256 + tid * 4);
                s.x += v.x; s.y += v.y; s.z += v.z; s.w += v.w;
            }
            *reinterpret_cast<float4*>(&ctcs[tid * 4]) = s;
        }
        __syncthreads();
        // register-lean update: 2 rows per thread, quads processed sequentially
#pragma unroll
        for (int rr = 0; rr < 2; ++rr) {
            const int ld = tid * 2 + rr;
            const int gd = ds * 256 + ld;
            float ob[16];
            load16(bold + ((size_t)b * DD + gd) * RR, ob);
            const float4* q0 = reinterpret_cast<const float4*>(
                g_Qpart + (((size_t)b * NSPL + 0) * DD + gd) * RR);
            const float4* q1 = reinterpret_cast<const float4*>(
                g_Qpart + (((size_t)b * NSPL + 1) * DD + gd) * RR);
#pragma unroll
            for (int sq = 0; sq < 4; ++sq) {
                float d0 = 0.f, d1 = 0.f, d2 = 0.f, d3 = 0.f;
#pragma unroll
                for (int r = 0; r < 16; ++r) {
                    float c = ob[r];
                    const float* row = &ctcs[r * 16 + sq * 4];
                    d0 = fmaf(c, row[0], d0);
                    d1 = fmaf(c, row[1], d1);
                    d2 = fmaf(c, row[2], d2);
                    d3 = fmaf(c, row[3], d3);
                }
                float4 qa = q0[sq], qb = q1[sq];
                float4 o;
                o.x = ob[4*sq+0] * (qa.x + qb.x) / (d0 + EPSV);
                o.y = ob[4*sq+1] * (qa.y + qb.y) / (d1 + EPSV);
                o.z = ob[4*sq+2] * (qa.z + qb.z) / (d2 + EPSV);
                o.w = ob[4*sq+3] * (qa.w + qb.w) / (d3 + EPSV);
                *reinterpret_cast<float4*>(&bss[ld * RR + sq * 4]) = o;
                *reinterpret_cast<float4*>(bnew + ((size_t)b * DD + gd) * RR + sq * 4) = o;
            }
        }
    } else {
        const float4* s = reinterpret_cast<const float4*>(
            bold + ((size_t)b * DD + (size_t)ds * 256) * RR);
        float4* d4 = reinterpret_cast<float4*>(bss);
#pragma unroll
        for (int i = 0; i < 8; ++i) d4[tid + i * 128] = s[tid + i * 128];
    }

    const float* xbase = x + (size_t)b * NN * DD + (size_t)ds * 256;
    const int srow = tid >> 2;                // 0..31 staging row base
    const int sc4  = tid & 3;                 // float4 col within 16-d tile
    const int ssw  = (srow >> 1) & 3;         // store swizzle
    const int rsw  = (tid >> 1) & 3;          // read swizzle

    // per-thread cp.async smem destinations (swizzled), buffer 0 base
    const uint32_t xs_base = smem_u32(xsb);

    u64 a0[8], a1[8], a2[8], a3[8];
#pragma unroll
    for (int q = 0; q < 8; ++q) { a0[q] = 0ull; a1[q] = 0ull; a2[q] = 0ull; a3[q] = 0ull; }

    // issue tile 0 into buffer 0
#pragma unroll
    for (int k = 0; k < 16; ++k)
        cp16(xs_base + (uint32_t)(((srow + k * 32) * 4 + (sc4 ^ ssw)) * 16),
             xbase + (size_t)(srow + k * 32) * DD + sc4 * 4);
    cp_commit();

    __syncthreads();   // bss ready (also covers UPD prologue smem)

#pragma unroll 1
    for (int t = 0; t < 16; ++t) {   // 16 tiles x 16 d = 256 d
        const uint32_t cur_off  = (uint32_t)((t & 1) * 2048 * 16);
        const uint32_t next_off = (uint32_t)(((t + 1) & 1) * 2048 * 16);
        if (t < 15) {
            // issue tile t+1 into the other buffer (overlaps compute below)
#pragma unroll
            for (int k = 0; k < 16; ++k)
                cp16(xs_base + next_off +
                         (uint32_t)(((srow + k * 32) * 4 + (sc4 ^ ssw)) * 16),
                     xbase + (size_t)(srow + k * 32) * DD + (t + 1) * 16 + sc4 * 4);
            cp_commit();
            cp_wait<1>();   // tile t landed
        } else {
            cp_wait<0>();
        }
        __syncthreads();    // make tile t visible to all warps

        const float4* xs4 = reinterpret_cast<const float4*>(
            reinterpret_cast<const char*>(xsb) + cur_off);
#pragma unroll
        for (int j4 = 0; j4 < 4; ++j4) {
            float4 x0 = xs4[(tid      ) * 4 + (j4 ^ rsw)];
            float4 x1 = xs4[(tid + 128) * 4 + (j4 ^ rsw)];
            float4 x2 = xs4[(tid + 256) * 4 + (j4 ^ rsw)];
            float4 x3 = xs4[(tid + 384) * 4 + (j4 ^ rsw)];
            const float* br = &bss[(t * 16 + j4 * 4) * RR];
            fma16_2_quad(a0, a1, a2, a3, packf2(x0.x,x0.x), packf2(x1.x,x1.x),
                         packf2(x2.x,x2.x), packf2(x3.x,x3.x), br);
            fma16_2_quad(a0, a1, a2, a3, packf2(x0.y,x0.y), packf2(x1.y,x1.y),
                         packf2(x2.y,x2.y), packf2(x3.y,x3.y), br + RR);
            fma16_2_quad(a0, a1, a2, a3, packf2(x0.z,x0.z), packf2(x1.z,x1.z),
                         packf2(x2.z,x2.z), packf2(x3.z,x3.z), br + 2 * RR);
            fma16_2_quad(a0, a1, a2, a3, packf2(x0.w,x0.w), packf2(x1.w,x1.w),
                         packf2(x2.w,x2.w), packf2(x3.w,x3.w), br + 3 * RR);
        }
        __syncthreads();    // done reading buf (t&1) before tile t+2 overwrites it
    }

    float acc[16];
    float* pbase = g_Ppart + (((size_t)b * NSLICE + ds) * NN) * RR;
    unpack_acc(a0, acc); store16(pbase + (size_t)(tid      ) * RR, acc);
    unpack_acc(a1, acc); store16(pbase + (size_t)(tid + 128) * RR, acc);
    unpack_acc(a2, acc); store16(pbase + (size_t)(tid + 256) * RR, acc);
    unpack_acc(a3, acc); store16(pbase + (size_t)(tid + 384) * RR, acc);

    // BtB gram partial from this slice's bases (256 rows)
#pragma unroll
    for (int k = 0; k < 2; ++k) {
        int p2 = tid + k * 128;
        int r = p2 >> 4, s2 = p2 & 15;
        float s0 = 0.f, s1 = 0.f, s2a = 0.f, s3 = 0.f;
#pragma unroll 4
        for (int i = 0; i < 256; i += 4) {
            s0  = fmaf(bss[(i+0)*16 + r], bss[(i+0)*16 + s2], s0);
            s1  = fmaf(bss[(i+1)*16 + r], bss[(i+1)*16 + s2], s1);
            s2a = fmaf(bss[(i+2)*16 + r], bss[(i+2)*16 + s2], s2a);
            s3  = fmaf(bss[(i+3)*16 + r], bss[(i+3)*16 + s2], s3);
        }
        g_btbp[((size_t)b * NBTB + ds) * 256 + p2] = (s0 + s1) + (s2a + s3);
    }
}

// ---------------- coef kernel: 32 n per block, 4 groups x 4 slices ----------------
// grid (16, BS), block 128
__device__ __forceinline__ void coef_body(bool init) {
    __shared__ float btbs[256];
    __shared__ __align__(16) float pg[4][32][16];
    __shared__ float smcf[32][17];
    const int tid = threadIdx.x;
    const int nc  = blockIdx.x;
    const int b   = blockIdx.y;

    if (tid < 64) {
        float4 s = make_float4(0.f, 0.f, 0.f, 0.f);
#pragma unroll
        for (int sl = 0; sl < NBTB; ++sl) {
            float4 v = *reinterpret_cast<const float4*>(
                g_btbp + ((size_t)b * NBTB + sl) * 256 + tid * 4);
            s.x += v.x; s.y += v.y; s.z += v.z; s.w += v.w;
        }
        *reinterpret_cast<float4*>(&btbs[tid * 4]) = s;
    }

    const int nl = tid & 31;
    const int g  = tid >> 5;
    const int n  = nc * 32 + nl;
    {
        float p[16];
#pragma unroll
        for (int r = 0; r < 16; ++r) p[r] = 0.f;
#pragma unroll
        for (int k = 0; k < 4; ++k) {
            const float4* pp = reinterpret_cast<const float4*>(
                g_Ppart + (((size_t)b * NSLICE + g * 4 + k) * NN + n) * RR);
#pragma unroll
            for (int q = 0; q < 4; ++q) {
                float4 v = pp[q];
                p[4*q+0] += v.x; p[4*q+1] += v.y; p[4*q+2] += v.z; p[4*q+3] += v.w;
            }
        }
        store16(&pg[g][nl][0], p);
    }
    __syncthreads();

    if (tid < 32) {
        float p[16];
#pragma unroll
        for (int r = 0; r < 16; ++r)
            p[r] = (pg[0][tid][r] + pg[1][tid][r]) + (pg[2][tid][r] + pg[3][tid][r]);

        const int nn = nc * 32 + tid;
        float cf[16];
        if (init) {
            float m = p[0];
#pragma unroll
            for (int r = 1; r < 16; ++r) m = fmaxf(m, p[r]);
            float s = 0.f;
#pragma unroll
            for (int r = 0; r < 16; ++r) { cf[r] = __expf(INVT * (p[r] - m)); s += cf[r]; }
            float inv = 1.f / s;
#pragma unroll
            for (int r = 0; r < 16; ++r) cf[r] *= inv;
        } else {
            load16(g_coef + ((size_t)b * NN + nn) * RR, cf);
        }
        float den[16];
        mat16(den, cf, btbs);
#pragma unroll
        for (int r = 0; r < 16; ++r) cf[r] = cf[r] * p[r] / (den[r] + EPSV);
        store16(g_coef + ((size_t)b * NN + nn) * RR, cf);
#pragma unroll
        for (int r = 0; r < 16; ++r) smcf[tid][r] = cf[r];
    }
    __syncthreads();

#pragma unroll
    for (int k = 0; k < 2; ++k) {
        int p2 = tid + k * 128;
        int r = p2 >> 4, s2 = p2 & 15;
        float s0 = 0.f, s1 = 0.f;
#pragma unroll
        for (int i = 0; i < 32; i += 2) {
            s0 = fmaf(smcf[i][r],   smcf[i][s2],   s0);
            s1 = fmaf(smcf[i+1][r], smcf[i+1][s2], s1);
        }
        g_ctcp[((size_t)b * NCTC + nc) * 256 + p2] = s0 + s1;
    }
}
__global__ void __launch_bounds__(128) k_coef_initupd() { coef_body(true); }
__global__ void __launch_bounds__(128) k_coef_upd()     { coef_body(false); }

// ---------------- Q pass: pure partial GEMM, split n 2 ways ----------------
// grid (16, 2, BS), block 128, 2 d per thread
__global__ void k_qmat(const float* __restrict__ x) {
    __shared__ __align__(16) float cfs[256 * RR];   // 16KB coef half
    const int tid = threadIdx.x;
    const int dc  = blockIdx.x;
    const int h   = blockIdx.y;
    const int b   = blockIdx.z;
    {
        const float4* s = reinterpret_cast<const float4*>(
            g_coef + ((size_t)b * NN + (size_t)h * 256) * RR);
        float4* dst = reinterpret_cast<float4*>(cfs);
#pragma unroll
        for (int i = 0; i < 8; ++i) dst[tid + i * 128] = s[tid + i * 128];
    }

    const int d = dc * 256 + tid * 2;
    const float* xb = x + ((size_t)b * NN + (size_t)h * 256) * DD + d;

    float2 xv0[8], xv1[8];
#pragma unroll
    for (int i = 0; i < 8; ++i) xv0[i] = *reinterpret_cast<const float2*>(xb + (size_t)i * DD);
#pragma unroll
    for (int i = 0; i < 8; ++i) xv1[i] = *reinterpret_cast<const float2*>(xb + (size_t)(8 + i) * DD);

    __syncthreads();

    u64 a0[8], a1[8];
#pragma unroll
    for (int q = 0; q < 8; ++q) { a0[q] = 0ull; a1[q] = 0ull; }

#pragma unroll 1
    for (int n0 = 0; n0 < 256; n0 += 16) {
        const bool pf = (n0 + 16) < 256;
#pragma unroll
        for (int i = 0; i < 8; ++i)
            fma16_2_dual(a0, a1, packf2(xv0[i].x, xv0[i].x), packf2(xv0[i].y, xv0[i].y),
                         &cfs[(n0 + i) * RR]);
        if (pf) {
#pragma unroll
            for (int i = 0; i < 8; ++i)
                xv0[i] = *reinterpret_cast<const float2*>(xb + (size_t)(n0 + 16 + i) * DD);
        }
#pragma unroll
        for (int i = 0; i < 8; ++i)
            fma16_2_dual(a0, a1, packf2(xv1[i].x, xv1[i].x), packf2(xv1[i].y, xv1[i].y),
                         &cfs[(n0 + 8 + i) * RR]);
        if (pf) {
#pragma unroll
            for (int i = 0; i < 8; ++i)
                xv1[i] = *reinterpret_cast<const float2*>(xb + (size_t)(n0 + 24 + i) * DD);
        }
    }

    float acc[16];
    unpack_acc(a0, acc);
    store16(g_Qpart + (((size_t)b * NSPL + h) * DD + d) * RR, acc);
    unpack_acc(a1, acc);
    store16(g_Qpart + (((size_t)b * NSPL + h) * DD + d + 1) * RR, acc);
}

// ---------------- reconstruction: 2 d per thread ----------------
// grid (16, BS), block 128
__global__ void k_out(const float* __restrict__ bfin, float* __restrict__ out) {
    __shared__ __align__(16) float cfs[NN * RR];
    const int tid = threadIdx.x;
    const int dc  = blockIdx.x;
    const int b   = blockIdx.y;
    {
        const float4* s = reinterpret_cast<const float4*>(g_coef + (size_t)b * NN * RR);
        float4* dst = reinterpret_cast<float4*>(cfs);
#pragma unroll
        for (int i = 0; i < 16; ++i) dst[tid + i * 128] = s[tid + i * 128];
    }
    __syncthreads();

    const int d = dc * 256 + tid * 2;
    float bsv[16];
    u64 b0[8], b1[8];
    load16(bfin + ((size_t)b * DD + d) * RR, bsv);
#pragma unroll
    for (int q = 0; q < 8; ++q) b0[q] = packf2(bsv[2*q], bsv[2*q+1]);
    load16(bfin + ((size_t)b * DD + d + 1) * RR, bsv);
#pragma unroll
    for (int q = 0; q < 8; ++q) b1[q] = packf2(bsv[2*q], bsv[2*q+1]);

    float* ob = out + (size_t)b * NN * DD + d;
#pragma unroll 2
    for (int n = 0; n < NN; ++n) {
        const ulonglong2* c2 = reinterpret_cast<const ulonglong2*>(&cfs[n * RR]);
        u64 s0a = 0ull, s0b = 0ull, s1a = 0ull, s1b = 0ull;
#pragma unroll
        for (int q = 0; q < 4; ++q) {
            ulonglong2 pq = c2[q];
            ffma2(s0a, b0[2*q+0], pq.x);
            ffma2(s0b, b0[2*q+1], pq.y);
            ffma2(s1a, b1[2*q+0], pq.x);
            ffma2(s1b, b1[2*q+1], pq.y);
        }
        float u0, u1, v0, v1, w0, w1, z0, z1;
        unpackf2(s0a, u0, u1); unpackf2(s0b, v0, v1);
        unpackf2(s1a, w0, w1); unpackf2(s1b, z0, z1);
        float2 o;
        o.x = (u0 + u1) + (v0 + v1);
        o.y = (w0 + w1) + (z0 + z1);
        *reinterpret_cast<float2*>(ob + (size_t)n * DD) = o;
    }
}

// ---------------- launch ----------------
extern "C" void kernel_launch(void* const* d_in, const int* in_sizes, int n_in,
                              void* d_out, int out_size) {
    (void)in_sizes; (void)n_in; (void)out_size;
    const float* x     = (const float*)d_in[0];
    const float* bases = (const float*)d_in[1];
    float* out = (float*)d_out;

    float* b0p; cudaGetSymbolAddress((void**)&b0p, g_b0);
    float* b1p; cudaGetSymbolAddress((void**)&b1p, g_b1);

    cudaFuncSetAttribute(k_pmat<false>, cudaFuncAttributeMaxDynamicSharedMemorySize, PM_SMEM_BYTES);
    cudaFuncSetAttribute(k_pmat<true>,  cudaFuncAttributeMaxDynamicSharedMemorySize, PM_SMEM_BYTES);

    // P(X, bases0) + BtB(bases0), then softmax init + coef update #1
    k_pmat<false><<<dim3(NSLICE, BS), 128, PM_SMEM_BYTES>>>(x, bases, nullptr);
    k_coef_initupd<<<dim3(16, BS), 128>>>();

    const float* boldp = bases;
    float* bnewp = b0p;
    for (int it = 0; it < 7; ++it) {
        k_qmat<<<dim3(16, NSPL, BS), 128>>>(x);                   // Q partials
        k_pmat<true><<<dim3(NSLICE, BS), 128, PM_SMEM_BYTES>>>(x, boldp, bnewp);
        k_coef_upd<<<dim3(16, BS), 128>>>();                      // coef upd + CtC
        boldp = bnewp;
        bnewp = (bnewp == b0p) ? b1p : b0p;
    }

    k_out<<<dim3(16, BS), 128>>>(boldp, out);
}